// round 14
// baseline (speedup 1.0000x reference)
#include <cuda_runtime.h>
#include <cuda_bf16.h>
#include <cstdint>

// Problem constants (fixed by dataset)
#define BATCH 16
#define NNODE 16384
#define DIM   128
#define NEDGE 65536
#define TOTAL_NODES (BATCH * NNODE)   // 262144
#define LN_EPS 1e-5f

// ---------------- device scratch (no allocs allowed) ----------------
__device__ __align__(16) float g_neigh[(size_t)TOTAL_NODES * DIM];   // aggregated features
__device__ __align__(16) float g_WT[256 * 128];                      // [Wself;Wneigh]^T: WT[k][n]
__device__ int   g_deg[NNODE];
__device__ int   g_rowstart[NNODE + 1];
__device__ int   g_cursor[NNODE];
__device__ int   g_csr[NEDGE];

// ---- canonical f32x2 helpers (proven in R11) ----
__device__ __forceinline__ unsigned long long pack_dup_f32(float a) {
    unsigned int u = __float_as_uint(a);
    unsigned long long out;
    asm("mov.b64 %0, {%1, %2};" : "=l"(out) : "r"(u), "r"(u));
    return out;
}
__device__ __forceinline__ void unpack_f32x2(unsigned long long in, float& lo, float& hi) {
    unsigned int ulo, uhi;
    asm("mov.b64 {%0, %1}, %2;" : "=r"(ulo), "=r"(uhi) : "l"(in));
    lo = __uint_as_float(ulo);
    hi = __uint_as_float(uhi);
}
__device__ __forceinline__ void fma_f32x2(unsigned long long& d,
                                          unsigned long long a,
                                          unsigned long long b) {
    asm("fma.rn.f32x2 %0, %1, %2, %3;" : "=l"(d) : "l"(a), "l"(b), "l"(d));
}

// ---- cp.async helpers (LDGSTS, base-arch sm_80+) ----
__device__ __forceinline__ uint32_t smem_u32(const void* p) {
    uint32_t a;
    asm("{ .reg .u64 t; cvta.to.shared.u64 t, %1; cvt.u32.u64 %0, t; }" : "=r"(a) : "l"(p));
    return a;
}
__device__ __forceinline__ void cpa16(uint32_t s, const void* g) {
    asm volatile("cp.async.ca.shared.global [%0], [%1], 16;" :: "r"(s), "l"(g));
}
#define CP_COMMIT() asm volatile("cp.async.commit_group;" ::: "memory")
#define CP_WAIT0()  asm volatile("cp.async.wait_group 0;" ::: "memory")

// ---------------- small setup kernels ----------------
__global__ void zero_kernel() {
    int i = blockIdx.x * blockDim.x + threadIdx.x;
    if (i < NNODE) { g_deg[i] = 0; g_cursor[i] = 0; }
}

// edge_index is int32 on the wire (JAX x64 disabled downcasts jnp.int64 -> int32).
__global__ void count_kernel(const int* __restrict__ edge) {
    int e = blockIdx.x * blockDim.x + threadIdx.x;
    if (e < NEDGE) atomicAdd(&g_deg[edge[NEDGE + e]], 1);
}

__global__ void scan_kernel() {
    __shared__ int sums[1024];
    int t = threadIdx.x;
    int base = t * 16;
    int local[16];
    int s = 0;
#pragma unroll
    for (int i = 0; i < 16; i++) { local[i] = s; s += g_deg[base + i]; }
    sums[t] = s;
    __syncthreads();
    for (int off = 1; off < 1024; off <<= 1) {
        int v = 0;
        if (t >= off) v = sums[t - off];
        __syncthreads();
        sums[t] += v;
        __syncthreads();
    }
    int excl = (t == 0) ? 0 : sums[t - 1];
#pragma unroll
    for (int i = 0; i < 16; i++) g_rowstart[base + i] = excl + local[i];
    if (t == 1023) g_rowstart[NNODE] = sums[1023];
}

__global__ void fill_kernel(const int* __restrict__ edge) {
    int e = blockIdx.x * blockDim.x + threadIdx.x;
    if (e < NEDGE) {
        int src = edge[e];
        int dst = edge[NEDGE + e];
        int pos = atomicAdd(&g_cursor[dst], 1);
        g_csr[g_rowstart[dst] + pos] = src;
    }
}

// transpose + concat weights: WT[k][n], k<128 -> Wself[n][k], k>=128 -> Wneigh[n][k-128]
__global__ void wt_kernel(const float* __restrict__ Ws, const float* __restrict__ Wn) {
    int idx = blockIdx.x * blockDim.x + threadIdx.x;
    if (idx < 256 * 128) {
        int k = idx >> 7, n = idx & 127;
        g_WT[idx] = (k < 128) ? Ws[n * 128 + k] : Wn[n * 128 + (k - 128)];
    }
}

// ---------------- neighbor mean via CSR gather, 4-way MLP ----------------
__global__ __launch_bounds__(256) void neigh_kernel(const float* __restrict__ x) {
    int gwarp = (blockIdx.x * 256 + threadIdx.x) >> 5;
    int lane = threadIdx.x & 31;
    int b = gwarp >> 14;
    int n = gwarp & (NNODE - 1);
    int s0 = g_rowstart[n];
    int s1 = g_rowstart[n + 1];
    const float* xb = x + ((size_t)b << 14) * DIM;
    float4 a0 = make_float4(0.f, 0.f, 0.f, 0.f);
    float4 a1 = a0, a2 = a0, a3 = a0;
    int j = s0;
    for (; j + 4 <= s1; j += 4) {
        int i0 = g_csr[j], i1 = g_csr[j + 1], i2 = g_csr[j + 2], i3 = g_csr[j + 3];
        float4 v0 = *(const float4*)(xb + (size_t)i0 * DIM + lane * 4);
        float4 v1 = *(const float4*)(xb + (size_t)i1 * DIM + lane * 4);
        float4 v2 = *(const float4*)(xb + (size_t)i2 * DIM + lane * 4);
        float4 v3 = *(const float4*)(xb + (size_t)i3 * DIM + lane * 4);
        a0.x += v0.x; a0.y += v0.y; a0.z += v0.z; a0.w += v0.w;
        a1.x += v1.x; a1.y += v1.y; a1.z += v1.z; a1.w += v1.w;
        a2.x += v2.x; a2.y += v2.y; a2.z += v2.z; a2.w += v2.w;
        a3.x += v3.x; a3.y += v3.y; a3.z += v3.z; a3.w += v3.w;
    }
    for (; j < s1; j++) {
        int i0 = g_csr[j];
        float4 v0 = *(const float4*)(xb + (size_t)i0 * DIM + lane * 4);
        a0.x += v0.x; a0.y += v0.y; a0.z += v0.z; a0.w += v0.w;
    }
    float4 acc;
    acc.x = (a0.x + a1.x) + (a2.x + a3.x);
    acc.y = (a0.y + a1.y) + (a2.y + a3.y);
    acc.z = (a0.z + a1.z) + (a2.z + a3.z);
    acc.w = (a0.w + a1.w) + (a2.w + a3.w);
    int deg = s1 - s0;
    float inv = 1.0f / (float)(deg > 0 ? deg : 1);
    acc.x *= inv; acc.y *= inv; acc.z *= inv; acc.w *= inv;
    *(float4*)(g_neigh + (size_t)gwarp * DIM + lane * 4) = acc;
}

// ---------------- fused dual-GEMM + bias + LayerNorm + ReLU ----------------
// tile 128x128, K=256 as 8 epochs of BK=32 (epochs 0-3: A=x, 4-7: A=g_neigh).
// cp.async double-buffered smem, 256 threads, 8x8 micro-tile, f32x2 FMA.
// smem layout (dynamic): As[2]: 128 x 36 floats (18432B each); Bs[2]: 32 x 136 floats (17408B each).
#define AS_STR 36
#define BS_STR 136
#define AS_BYTES (128 * AS_STR * 4)          // 18432
#define BS_BYTES (32 * BS_STR * 4)           // 17408
#define OFF_AS0  0
#define OFF_AS1  AS_BYTES
#define OFF_BS0  (2 * AS_BYTES)
#define OFF_BS1  (2 * AS_BYTES + BS_BYTES)
#define SMEM_DYN (2 * AS_BYTES + 2 * BS_BYTES)   // 71680

__global__ __launch_bounds__(256, 2) void gemm_ln_kernel(
    const float* __restrict__ x,
    const float* __restrict__ bias,
    const float* __restrict__ gamma,
    const float* __restrict__ beta,
    float* __restrict__ out)
{
    extern __shared__ __align__(16) char smx[];
    float* Asm = (float*)smx;

    int tid = threadIdx.x;
    int tx = tid & 15;     // col group: cols tx*8 .. tx*8+7
    int ty = tid >> 4;     // row group: rows ty*8 .. ty*8+7
    int row0 = blockIdx.x * 128;
    uint32_t smb = smem_u32(smx);

    // per-thread load mapping
    int ar = tid >> 1;                 // A row 0..127
    int ac = (tid & 1) * 16;           // A col group (16 floats)
    int bk = tid >> 3;                 // B k-row 0..31
    int bc = (tid & 7) * 16;           // B col group (16 floats)
    uint32_t as_base[2] = { smb + OFF_AS0 + (uint32_t)(ar * AS_STR + ac) * 4,
                            smb + OFF_AS1 + (uint32_t)(ar * AS_STR + ac) * 4 };
    uint32_t bs_base[2] = { smb + OFF_BS0 + (uint32_t)(bk * BS_STR + bc) * 4,
                            smb + OFF_BS1 + (uint32_t)(bk * BS_STR + bc) * 4 };

    unsigned long long acc[8][4];
#pragma unroll
    for (int i = 0; i < 8; i++)
#pragma unroll
        for (int j = 0; j < 4; j++) acc[i][j] = 0ull;

    // issue loads for epoch e into buffer e&1
    auto issue = [&](int e) {
        int ph = e >> 2, kc = e & 3, buf = e & 1;
        const float* Aep = (ph ? g_neigh : x) + (size_t)row0 * DIM + kc * 32;
        const float* Ag = Aep + (size_t)ar * DIM + ac;
        uint32_t as = as_base[buf];
#pragma unroll
        for (int q = 0; q < 4; q++) cpa16(as + q * 16, Ag + q * 4);
        const float* Bg = g_WT + (size_t)(ph * 128 + kc * 32 + bk) * 128 + bc;
        uint32_t bs = bs_base[buf];
#pragma unroll
        for (int q = 0; q < 4; q++) cpa16(bs + q * 16, Bg + q * 4);
        CP_COMMIT();
    };

    issue(0);

#pragma unroll 1
    for (int e = 0; e < 8; e++) {
        CP_WAIT0();
        __syncthreads();            // buffer e&1 fully populated & visible; prior readers done
        if (e < 7) issue(e + 1);    // prefetch into the other buffer, hidden under FMAs

        const float* As = (const float*)(smx + ((e & 1) ? OFF_AS1 : OFF_AS0));
        const char*  Bs = smx + ((e & 1) ? OFF_BS1 : OFF_BS0);
#pragma unroll
        for (int k = 0; k < 32; k++) {
            ulonglong2 p0 = *(const ulonglong2*)(Bs + (size_t)k * (BS_STR * 4) + tx * 32);
            ulonglong2 p1 = *(const ulonglong2*)(Bs + (size_t)k * (BS_STR * 4) + tx * 32 + 16);
            unsigned long long b[4] = { p0.x, p0.y, p1.x, p1.y };
#pragma unroll
            for (int i = 0; i < 8; i++) {
                unsigned long long a2 = pack_dup_f32(As[(ty * 8 + i) * AS_STR + k]);
#pragma unroll
                for (int j = 0; j < 4; j++) fma_f32x2(acc[i][j], a2, b[j]);
            }
        }
        __syncthreads();            // all reads of buffer e&1 done before epoch e+2 overwrites it
    }

    // epilogue: bias -> LayerNorm over 128 cols (16 contiguous lanes per row) -> relu
    float bi[8], ga[8], be[8];
#pragma unroll
    for (int j = 0; j < 8; j++) {
        int col = tx * 8 + j;
        bi[j] = bias[col]; ga[j] = gamma[col]; be[j] = beta[col];
    }

#pragma unroll
    for (int i = 0; i < 8; i++) {
        float c[8];
#pragma unroll
        for (int j = 0; j < 4; j++) unpack_f32x2(acc[i][j], c[2 * j], c[2 * j + 1]);
#pragma unroll
        for (int j = 0; j < 8; j++) c[j] += bi[j];

        float s = 0.f;
#pragma unroll
        for (int j = 0; j < 8; j++) s += c[j];
#pragma unroll
        for (int m = 1; m < 16; m <<= 1) s += __shfl_xor_sync(0xffffffffu, s, m);
        float mean = s * (1.0f / 128.0f);

        float sq = 0.f;
#pragma unroll
        for (int j = 0; j < 8; j++) { float d = c[j] - mean; sq += d * d; }
#pragma unroll
        for (int m = 1; m < 16; m <<= 1) sq += __shfl_xor_sync(0xffffffffu, sq, m);
        float rstd = rsqrtf(sq * (1.0f / 128.0f) + LN_EPS);

        float4 o0, o1;
        float v;
        v = (c[0] - mean) * rstd * ga[0] + be[0]; o0.x = fmaxf(v, 0.f);
        v = (c[1] - mean) * rstd * ga[1] + be[1]; o0.y = fmaxf(v, 0.f);
        v = (c[2] - mean) * rstd * ga[2] + be[2]; o0.z = fmaxf(v, 0.f);
        v = (c[3] - mean) * rstd * ga[3] + be[3]; o0.w = fmaxf(v, 0.f);
        v = (c[4] - mean) * rstd * ga[4] + be[4]; o1.x = fmaxf(v, 0.f);
        v = (c[5] - mean) * rstd * ga[5] + be[5]; o1.y = fmaxf(v, 0.f);
        v = (c[6] - mean) * rstd * ga[6] + be[6]; o1.z = fmaxf(v, 0.f);
        v = (c[7] - mean) * rstd * ga[7] + be[7]; o1.w = fmaxf(v, 0.f);

        size_t row = (size_t)(row0 + ty * 8 + i);
        *(float4*)(out + row * DIM + tx * 8)     = o0;
        *(float4*)(out + row * DIM + tx * 8 + 4) = o1;
    }
}

// ---------------- launch ----------------
extern "C" void kernel_launch(void* const* d_in, const int* in_sizes, int n_in,
                              void* d_out, int out_size)
{
    const float* x = nullptr;
    const int* edge = nullptr;          // int32 on the wire
    const float* Ws = nullptr; const float* Wn = nullptr;
    const float* bias = nullptr; const float* gamma = nullptr; const float* beta = nullptr;
    int w_seen = 0, v_seen = 0;
    for (int i = 0; i < n_in; i++) {
        int sz = in_sizes[i];
        if (sz == TOTAL_NODES * DIM) {
            x = (const float*)d_in[i];
        } else if (sz == 2 * NEDGE) {
            edge = (const int*)d_in[i];
        } else if (sz == 128 * 128) {
            if (w_seen == 0) Ws = (const float*)d_in[i];
            else             Wn = (const float*)d_in[i];
            w_seen++;
        } else if (sz == 128) {
            if (v_seen == 0)      bias  = (const float*)d_in[i];
            else if (v_seen == 1) gamma = (const float*)d_in[i];
            else                  beta  = (const float*)d_in[i];
            v_seen++;
        }
    }
    float* out = (float*)d_out;

    cudaFuncSetAttribute(gemm_ln_kernel, cudaFuncAttributeMaxDynamicSharedMemorySize, SMEM_DYN);

    // 1. CSR build (edge structure is batch-invariant)
    zero_kernel<<<(NNODE + 255) / 256, 256>>>();
    count_kernel<<<(NEDGE + 255) / 256, 256>>>(edge);
    scan_kernel<<<1, 1024>>>();
    fill_kernel<<<(NEDGE + 255) / 256, 256>>>(edge);

    // 2. transpose+concat weights
    wt_kernel<<<(256 * 128 + 255) / 256, 256>>>(Ws, Wn);

    // 3. neighbor mean (gather via CSR, MLP-4 inner loop)
    neigh_kernel<<<TOTAL_NODES / 8, 256>>>(x);

    // 4. fused dual-GEMM + bias + LayerNorm + ReLU (cp.async double-buffered, f32x2)
    gemm_ln_kernel<<<TOTAL_NODES / 128, 256, SMEM_DYN>>>(x, bias, gamma, beta, out);
}